// round 12
// baseline (speedup 1.0000x reference)
#include <cuda_runtime.h>
#include <cuda_fp16.h>
#include <cstdint>
#include <math.h>

// Shapes: B=16384, Q=1024, F=2, D=5
#define NB 16384

// ---------------- scratch (device globals; no allocs allowed) ----------------
__device__ __align__(16) __half g_ha1[(size_t)NB * 4096];  // gelu(LN(...)) fp16
__device__ __align__(16) __half g_h2 [(size_t)NB * 2048];  // G2 out (pre-LN) fp16
__device__ __align__(16) __half g_ha2[(size_t)NB * 2048];  // tanh(LN(h2)) fp16
__device__ __align__(16) __half g_hp1[(size_t)NB * 2048];  // silu(LN(...)) fp16
__device__ __align__(16) __half g_amp[(size_t)NB * 1024];  // amp fp16
__device__ __align__(16) __half g_hqs[(size_t)NB * 1024];  // qs fp16
__device__ __align__(16) __half g_hw [13631488];           // half weights: W2|W3|phW2|Wo
__device__ __align__(16) __half g_hwt[1048576];            // Wv^T fp16
__device__ __align__(16) __half g_hwc[1048576];            // Wc = Wo @ Wv fp16
__device__ __align__(16) float  g_bc [1024];               // bc = Wo@bv + bo
__device__ __align__(16) float4 g_rot4[1024];              // (rf0, rp0, rf1, rp1) per col
__device__ __align__(16) float  g_rz3[1024];               // tanh(rp2)/3 per col
__device__ __align__(16) float  g_stats[18];               // 9 LN moments x 2 nets

// ---------------- helpers ----------------
__device__ __forceinline__ uint32_t smem_u32(const void* p) {
    uint32_t a;
    asm("{ .reg .u64 t; cvta.to.shared.u64 t, %1; cvt.u32.u64 %0, t; }" : "=r"(a) : "l"(p));
    return a;
}
__device__ __forceinline__ void cpa16(uint32_t saddr, const void* g) {
    asm volatile("cp.async.cg.shared.global [%0], [%1], 16;\n" :: "r"(saddr), "l"(g));
}
__device__ __forceinline__ void ldsm4(uint32_t* r, uint32_t addr) {
    asm volatile("ldmatrix.sync.aligned.m8n8.x4.shared.b16 {%0,%1,%2,%3}, [%4];"
                 : "=r"(r[0]), "=r"(r[1]), "=r"(r[2]), "=r"(r[3]) : "r"(addr));
}
__device__ __forceinline__ void mma16(float* c, const uint32_t* a, const uint32_t* b) {
    asm volatile(
        "mma.sync.aligned.m16n8k16.row.col.f32.f16.f16.f32 "
        "{%0,%1,%2,%3}, {%4,%5,%6,%7}, {%8,%9}, {%0,%1,%2,%3};\n"
        : "+f"(c[0]), "+f"(c[1]), "+f"(c[2]), "+f"(c[3])
        : "r"(a[0]), "r"(a[1]), "r"(a[2]), "r"(a[3]), "r"(b[0]), "r"(b[1]));
}
__device__ __forceinline__ float tanhfast(float x) {
    float r;
    asm("tanh.approx.f32 %0, %1;" : "=f"(r) : "f"(x));
    return r;
}
// A&S 7.1.26 erf approximation, |err| <= 1.5e-7
__device__ __forceinline__ float erf_fast(float x) {
    const float ax = fabsf(x);
    const float t = __frcp_rn(fmaf(0.3275911f, ax, 1.0f));
    float p = fmaf(1.061405429f, t, -1.453152027f);
    p = fmaf(p, t, 1.421413741f);
    p = fmaf(p, t, -0.284496736f);
    p = fmaf(p, t, 0.254829592f);
    p *= t;
    const float y = 1.0f - p * __expf(-ax * ax);
    return copysignf(y, x);
}

// ---------------- GEMM: C(M,N) = epi(A(M,K) @ W(N,K)^T + bias) ----------------
// fp16 in, fp32 accum, mma.sync m16n8k16. CTA 256x128, k-chunk 128 halves
// (256B row + 16B pad = 272B, conflict-free). 512 thr = 16 warps (8m x 2n),
// warp 32x64. 2-stage pipeline (209 KB smem).
// EPI: 0 = +bias -> float C; 1 = +bias -> half C;
//      2 = +bias, tanh -> qs-mix (rot4/rz3 tables) -> half C; 3 = no bias -> half C
#define ROWB 272
#define STGB (384 * ROWB)       // A 256 rows + B 128 rows = 104448 B / stage
#define NSTG 2
#define GEMM_SMEM (NSTG * STGB) // 208896

template<int EPI>
__global__ void __launch_bounds__(512, 1)
gemm_fp16(const __half* __restrict__ A, const __half* __restrict__ W,
          const float* __restrict__ bias, void* __restrict__ Cv, int N, int K,
          const __half* __restrict__ amp, const float4* __restrict__ rot4,
          const float* __restrict__ rz3) {
    extern __shared__ __align__(128) char smem[];
    const uint32_t sb = smem_u32(smem);
    const int tid = threadIdx.x, lane = tid & 31, warp = tid >> 5;
    const int wm = warp >> 1, wn = warp & 1;
    const int g = lane >> 2, tg = lane & 3;
    const int m0 = blockIdx.y * 256, n0 = blockIdx.x * 128;

    // ldmatrix per-lane byte offsets within a stage (add ks*32 at use)
    uint32_t aoff[2], boff[4];
    {
        const int arow = lane & 15, aseg = lane >> 4;
        #pragma unroll
        for (int mi = 0; mi < 2; mi++)
            aoff[mi] = (uint32_t)((wm * 32 + mi * 16 + arow) * ROWB + aseg * 16);
        const int nrow = ((lane >> 4) << 3) + (lane & 7);
        const int bseg = (lane >> 3) & 1;
        #pragma unroll
        for (int p = 0; p < 4; p++)
            boff[p] = (uint32_t)(256 * ROWB + (wn * 64 + p * 16 + nrow) * ROWB + bseg * 16);
    }

    float acc[2][8][4];
    #pragma unroll
    for (int i = 0; i < 2; i++)
        #pragma unroll
        for (int j = 0; j < 8; j++)
            #pragma unroll
            for (int k = 0; k < 4; k++) acc[i][j][k] = 0.0f;

    const int nt = K >> 7;   // k-chunks of 128 halves

    auto load_stage = [&](int t) {
        const uint32_t dst = sb + (uint32_t)(t & 1) * STGB;
        // 384 rows x 16 chunks of 16B = 6144 chunks, 12 per thread
        #pragma unroll
        for (int i = 0; i < 12; i++) {
            const int cid = i * 512 + tid;
            const int r = cid >> 4, c = cid & 15;
            const __half* src = (r < 256)
                ? (A + (size_t)(m0 + r) * K + t * 128 + c * 8)
                : (W + (size_t)(n0 + r - 256) * K + t * 128 + c * 8);
            cpa16(dst + (uint32_t)(r * ROWB + c * 16), src);
        }
        asm volatile("cp.async.commit_group;\n" ::: "memory");
    };

    load_stage(0);

    for (int t = 0; t < nt; t++) {
        asm volatile("cp.async.wait_group 0;\n" ::: "memory");
        __syncthreads();
        if (t + 1 < nt) load_stage(t + 1);
        const uint32_t stg = sb + (uint32_t)(t & 1) * STGB;
        #pragma unroll
        for (int ks = 0; ks < 8; ks++) {   // 8 x k16 per chunk
            uint32_t af[2][4], bf[4][4];
            #pragma unroll
            for (int mi = 0; mi < 2; mi++) ldsm4(af[mi], stg + aoff[mi] + ks * 32);
            #pragma unroll
            for (int p = 0; p < 4; p++) ldsm4(bf[p], stg + boff[p] + ks * 32);
            #pragma unroll
            for (int mi = 0; mi < 2; mi++)
                #pragma unroll
                for (int ni = 0; ni < 8; ni++)
                    mma16(acc[mi][ni], af[mi], &bf[ni >> 1][(ni & 1) * 2]);
        }
        __syncthreads();
    }

    // -------- epilogue --------
    #pragma unroll
    for (int mi = 0; mi < 2; mi++) {
        #pragma unroll
        for (int half_ = 0; half_ < 2; half_++) {
            const int row = m0 + wm * 32 + mi * 16 + g + half_ * 8;
            #pragma unroll
            for (int ni = 0; ni < 8; ni++) {
                const int col = n0 + wn * 64 + ni * 8 + tg * 2;
                float v0 = acc[mi][ni][half_ * 2 + 0];
                float v1 = acc[mi][ni][half_ * 2 + 1];
                if (EPI != 3) { v0 += bias[col]; v1 += bias[col + 1]; }
                if (EPI == 0) {
                    float* C = (float*)Cv;
                    *(float2*)&C[(size_t)row * N + col] = make_float2(v0, v1);
                } else if (EPI == 2) {
                    #pragma unroll
                    for (int e = 0; e < 2; e++) {
                        float& v = e ? v1 : v0;
                        const int cc = col + e;
                        const float4 rr = rot4[cc];
                        const float phase = tanhfast(v);
                        const float a = __half2float(amp[(size_t)row * 1024 + cc]);
                        const float rx = __sinf(fmaf(a, rr.x, rr.y));
                        const float ry = __cosf(fmaf(phase, rr.z, rr.w));
                        v = fmaf(rx + ry, (1.0f / 3.0f), rz3[cc]);
                    }
                    __half* C = (__half*)Cv;
                    *(__half2*)&C[(size_t)row * N + col] = __floats2half2_rn(v0, v1);
                } else {
                    __half* C = (__half*)Cv;
                    *(__half2*)&C[(size_t)row * N + col] = __floats2half2_rn(v0, v1);
                }
            }
        }
    }
}

// ---------------- block reduce helper (256-thread blocks) ----------------
__device__ __forceinline__ void blk_reduce2(float& s, float& ss) {
    __shared__ float sh[16];
    #pragma unroll
    for (int o = 16; o; o >>= 1) {
        s  += __shfl_xor_sync(0xFFFFFFFFu, s, o);
        ss += __shfl_xor_sync(0xFFFFFFFFu, ss, o);
    }
    int w = threadIdx.x >> 5, l = threadIdx.x & 31;
    if (l == 0) { sh[w] = s; sh[w + 8] = ss; }
    __syncthreads();
    if (threadIdx.x < 32) {
        float a = (l < 8) ? sh[l] : 0.0f;
        float b = (l < 8) ? sh[l + 8] : 0.0f;
        #pragma unroll
        for (int o = 4; o; o >>= 1) {
            a += __shfl_xor_sync(0xFFFFFFFFu, a, o);
            b += __shfl_xor_sync(0xFFFFFFFFu, b, o);
        }
        if (l == 0) { sh[0] = a; sh[1] = b; }
    }
    __syncthreads();
    s = sh[0]; ss = sh[1];
}

// ------------- rank-2 input layer, closed-form LN stats -------------
// ACT: 0 = gelu(fast erf), 1 = silu (fast exp).
template<int ACT, int NCOLS>
__global__ __launch_bounds__(256)
void rank2_ln_act(const float* __restrict__ x, const float* __restrict__ W,
                  const float* __restrict__ b, const float* __restrict__ gam,
                  const float* __restrict__ bet, const float* __restrict__ st,
                  __half* __restrict__ out) {
    const int row = blockIdx.x;
    const float x0 = x[row * 2], x1 = x[row * 2 + 1];
    const float mean = fmaf(x0, st[0], fmaf(x1, st[1], st[2]));
    const float var  = fmaf(x0 * x0, st[3], fmaf(x1 * x1, st[4], st[5]))
                     + 2.0f * fmaf(x0 * x1, st[6], fmaf(x0, st[7], x1 * st[8]));
    const float rstd = rsqrtf(var + 1e-5f);
    constexpr int PER2 = NCOLS / 512;
    #pragma unroll
    for (int i = 0; i < PER2; i++) {
        const int j = i * 256 + threadIdx.x;          // pair index
        const float4 w = *(const float4*)&W[4 * j];   // cols 2j, 2j+1
        const float2 bb = *(const float2*)&b[2 * j];
        const float2 gg = *(const float2*)&gam[2 * j];
        const float2 be = *(const float2*)&bet[2 * j];
        const float y0 = fmaf(x0, w.x, fmaf(x1, w.y, bb.x));
        const float y1 = fmaf(x0, w.z, fmaf(x1, w.w, bb.y));
        float r[2];
        #pragma unroll
        for (int e = 0; e < 2; e++) {
            const float v = ((e ? y1 : y0) - mean) * rstd * (e ? gg.y : gg.x)
                          + (e ? be.y : be.x);
            if (ACT == 0) r[e] = 0.5f * v * (1.0f + erf_fast(v * 0.70710678118654752f));
            else          r[e] = v * __fdividef(1.0f, 1.0f + __expf(-v));
        }
        *(__half2*)&out[(size_t)row * NCOLS + 2 * j] = __floats2half2_rn(r[0], r[1]);
    }
}

// ------------- LN + tanh (rows of 2048): fp16 in, fp16 out -------------
__global__ __launch_bounds__(256)
void ln_tanh2048(const __half* __restrict__ d, const float* __restrict__ gam,
                 const float* __restrict__ bet, __half* __restrict__ out) {
    const int row = blockIdx.x;
    float y[8];
    float s = 0.0f, ss = 0.0f;
    #pragma unroll
    for (int i = 0; i < 4; i++) {
        const int j = i * 256 + threadIdx.x;          // pair index
        const float2 v = __half22float2(*(const __half2*)&d[(size_t)row * 2048 + 2 * j]);
        y[2*i] = v.x; y[2*i+1] = v.y;
        s += v.x + v.y; ss += v.x * v.x + v.y * v.y;
    }
    blk_reduce2(s, ss);
    const float mean = s * (1.0f / 2048.0f);
    const float var  = ss * (1.0f / 2048.0f) - mean * mean;
    const float rstd = rsqrtf(var + 1e-5f);
    #pragma unroll
    for (int i = 0; i < 4; i++) {
        const int j = i * 256 + threadIdx.x;
        const float2 gg = *(const float2*)&gam[2 * j];
        const float2 be = *(const float2*)&bet[2 * j];
        const float r0 = tanhfast((y[2*i]   - mean) * rstd * gg.x + be.x);
        const float r1 = tanhfast((y[2*i+1] - mean) * rstd * gg.y + be.y);
        *(__half2*)&out[(size_t)row * 2048 + 2 * j] = __floats2half2_rn(r0, r1);
    }
}

// ------------- merged prep: weight fp16 copies + Wv transpose + rot tables + LN stats ----
__global__ __launch_bounds__(256)
void prep_weights(const float* __restrict__ W2, const float* __restrict__ W3,
                  const float* __restrict__ phW2, const float* __restrict__ Wo,
                  const float* __restrict__ Wv,
                  const float* __restrict__ aW1, const float* __restrict__ ab1,
                  const float* __restrict__ pW1, const float* __restrict__ pb1,
                  const float* __restrict__ rf, const float* __restrict__ rp,
                  __half* __restrict__ hw, __half* __restrict__ hwt,
                  float4* __restrict__ rot4, float* __restrict__ rz3,
                  float* __restrict__ stats) {
    const int bid = blockIdx.x;
    if (bid < 13312) {
        const float4* src; __half2* dst; int off;
        if (bid < 8192)       { src = (const float4*)W2;   dst = (__half2*)(hw);            off = bid; }
        else if (bid < 10240) { src = (const float4*)W3;   dst = (__half2*)(hw + 8388608);  off = bid - 8192; }
        else if (bid < 12288) { src = (const float4*)phW2; dst = (__half2*)(hw + 10485760); off = bid - 10240; }
        else                  { src = (const float4*)Wo;   dst = (__half2*)(hw + 12582912); off = bid - 12288; }
        const int i = off * 256 + threadIdx.x;
        float4 v = src[i];
        dst[2*i]   = __floats2half2_rn(v.x, v.y);
        dst[2*i+1] = __floats2half2_rn(v.z, v.w);
    } else if (bid < 14336) {
        __shared__ float t[32][33];
        const int tb = bid - 13312;
        const int bx = (tb & 31) * 32, by = (tb >> 5) * 32;
        const int tx = threadIdx.x & 31, ty = threadIdx.x >> 5;  // 32 x 8
        #pragma unroll
        for (int i = 0; i < 32; i += 8)
            t[ty + i][tx] = Wv[(size_t)(by + ty + i) * 1024 + bx + tx];
        __syncthreads();
        #pragma unroll
        for (int i = 0; i < 32; i += 8)
            hwt[(size_t)(bx + ty + i) * 1024 + by + tx] = __float2half_rn(t[tx][ty + i]);
    } else if (bid < 14338) {
        // LN weight moments in fp64
        const int net = bid - 14336;
        const float* W = net ? pW1 : aW1;
        const float* b = net ? pb1 : ab1;
        const int N = net ? 2048 : 4096;
        double a[9] = {0,0,0,0,0,0,0,0,0};
        for (int j = threadIdx.x; j < N; j += 256) {
            const double w0 = W[2*j], w1 = W[2*j+1], bb = b[j];
            a[0] += w0;    a[1] += w1;    a[2] += bb;
            a[3] += w0*w0; a[4] += w1*w1; a[5] += bb*bb;
            a[6] += w0*w1; a[7] += w0*bb; a[8] += w1*bb;
        }
        __shared__ double sh[8][9];
        const int lane = threadIdx.x & 31, w = threadIdx.x >> 5;
        #pragma unroll
        for (int k = 0; k < 9; k++)
            #pragma unroll
            for (int o = 16; o; o >>= 1)
                a[k] += __shfl_down_sync(0xFFFFFFFFu, a[k], o);
        if (lane == 0)
            #pragma unroll
            for (int k = 0; k < 9; k++) sh[w][k] = a[k];
        __syncthreads();
        if (threadIdx.x == 0) {
            double S[9];
            #pragma unroll
            for (int k = 0; k < 9; k++) {
                S[k] = 0.0;
                for (int ww = 0; ww < 8; ww++) S[k] += sh[ww][k];
            }
            const double inv = 1.0 / N;
            const double m0 = S[0]*inv, m1 = S[1]*inv, mb = S[2]*inv;
            float* st = stats + 9 * net;
            st[0] = (float)m0; st[1] = (float)m1; st[2] = (float)mb;
            st[3] = (float)(S[3]*inv - m0*m0);
            st[4] = (float)(S[4]*inv - m1*m1);
            st[5] = (float)(S[5]*inv - mb*mb);
            st[6] = (float)(S[6]*inv - m0*m1);
            st[7] = (float)(S[7]*inv - m0*mb);
            st[8] = (float)(S[8]*inv - m1*mb);
        }
    } else {
        // rot tables (d = 4 slice)
        for (int j = threadIdx.x; j < 1024; j += 256) {
            const int base = (4 * 1024 + j) * 3;
            rot4[j] = make_float4(rf[base], rp[base], rf[base + 1], rp[base + 1]);
            rz3[j]  = tanhf(rp[base + 2]) * (1.0f / 3.0f);
        }
    }
}

// ------------- bc = Wo @ bv + bo (fp32) -------------
__global__ __launch_bounds__(256)
void bc_kernel(const float* __restrict__ Wo, const float* __restrict__ bv,
               const float* __restrict__ bo, float* __restrict__ bc) {
    const int row = blockIdx.x;
    float s = 0.0f, ss = 0.0f;
    for (int k = threadIdx.x; k < 1024; k += 256)
        s += Wo[(size_t)row * 1024 + k] * bv[k];
    blk_reduce2(s, ss);
    if (threadIdx.x == 0) bc[row] = s + bo[row];
}

// ---------------- launch ----------------
extern "C" void kernel_launch(void* const* d_in, const int* in_sizes, int n_in,
                              void* d_out, int out_size) {
    const float* x        = (const float*)d_in[0];
    const float* amp_W1   = (const float*)d_in[1];
    const float* amp_b1   = (const float*)d_in[2];
    const float* amp_g1   = (const float*)d_in[3];
    const float* amp_be1  = (const float*)d_in[4];
    const float* amp_W2   = (const float*)d_in[5];
    const float* amp_b2   = (const float*)d_in[6];
    const float* amp_g2   = (const float*)d_in[7];
    const float* amp_be2  = (const float*)d_in[8];
    const float* amp_W3   = (const float*)d_in[9];
    const float* amp_b3   = (const float*)d_in[10];
    const float* ph_W1    = (const float*)d_in[11];
    const float* ph_b1    = (const float*)d_in[12];
    const float* ph_g1    = (const float*)d_in[13];
    const float* ph_be1   = (const float*)d_in[14];
    const float* ph_W2    = (const float*)d_in[15];
    const float* ph_b2    = (const float*)d_in[16];
    const float* rot_freq = (const float*)d_in[17];
    const float* rot_phase= (const float*)d_in[18];
    const float* attn_in_w= (const float*)d_in[19];
    const float* attn_in_b= (const float*)d_in[20];
    const float* attn_out_w=(const float*)d_in[21];
    const float* attn_out_b=(const float*)d_in[22];

    float *bc, *rz3, *stats;
    float4* rot4;
    __half *ha1, *h2, *ha2, *hp1, *amp, *hqs, *hw, *hwt, *hwc;
    cudaGetSymbolAddress((void**)&ha1, g_ha1);
    cudaGetSymbolAddress((void**)&h2,  g_h2);
    cudaGetSymbolAddress((void**)&ha2, g_ha2);
    cudaGetSymbolAddress((void**)&hp1, g_hp1);
    cudaGetSymbolAddress((void**)&amp, g_amp);
    cudaGetSymbolAddress((void**)&hqs, g_hqs);
    cudaGetSymbolAddress((void**)&hw,  g_hw);
    cudaGetSymbolAddress((void**)&hwt, g_hwt);
    cudaGetSymbolAddress((void**)&hwc, g_hwc);
    cudaGetSymbolAddress((void**)&bc,  g_bc);
    cudaGetSymbolAddress((void**)&rot4, g_rot4);
    cudaGetSymbolAddress((void**)&rz3, g_rz3);
    cudaGetSymbolAddress((void**)&stats, g_stats);

    __half* hW2   = hw;
    __half* hW3   = hw + 8388608;
    __half* hphW2 = hw + 10485760;
    __half* hWo   = hw + 12582912;
    const float* Wv = attn_in_w + (size_t)2048 * 1024;
    const float* bv = attn_in_b + 2048;

    cudaFuncSetAttribute(gemm_fp16<0>, cudaFuncAttributeMaxDynamicSharedMemorySize, GEMM_SMEM);
    cudaFuncSetAttribute(gemm_fp16<1>, cudaFuncAttributeMaxDynamicSharedMemorySize, GEMM_SMEM);
    cudaFuncSetAttribute(gemm_fp16<2>, cudaFuncAttributeMaxDynamicSharedMemorySize, GEMM_SMEM);
    cudaFuncSetAttribute(gemm_fp16<3>, cudaFuncAttributeMaxDynamicSharedMemorySize, GEMM_SMEM);

    // 1: merged prep (weights, transpose, rot tables, LN stats)
    prep_weights<<<14339, 256>>>(amp_W2, amp_W3, ph_W2, attn_out_w, Wv,
                                 amp_W1, amp_b1, ph_W1, ph_b1, rot_freq, rot_phase,
                                 hw, hwt, rot4, rz3, stats);
    // 2: Wc = Wo @ Wv (A=hWo, W=hWv^T), half out
    gemm_fp16<3><<<dim3(8, 4), 512, GEMM_SMEM>>>(hWo, hwt, nullptr, hwc, 1024, 1024,
                                                 nullptr, nullptr, nullptr);
    // 3: amp input layer (closed-form LN, fast erf)
    rank2_ln_act<0, 4096><<<NB, 256>>>(x, amp_W1, amp_b1, amp_g1, amp_be1, stats, ha1);
    // 4: G2 (big GEMM -> ncu captured slot)
    gemm_fp16<1><<<dim3(16, 64), 512, GEMM_SMEM>>>(ha1, hW2, amp_b2, h2, 2048, 4096,
                                                   nullptr, nullptr, nullptr);
    // 5: phase input layer
    rank2_ln_act<1, 2048><<<NB, 256>>>(x, ph_W1, ph_b1, ph_g1, ph_be1, stats + 9, hp1);
    // 6: LN + tanh
    ln_tanh2048<<<NB, 256>>>(h2, amp_g2, amp_be2, ha2);
    // 7: G3 -> amp (fp16)
    gemm_fp16<1><<<dim3(8, 64), 512, GEMM_SMEM>>>(ha2, hW3, amp_b3, amp, 1024, 2048,
                                                  nullptr, nullptr, nullptr);
    // 8: bc = Wo@bv + bo
    bc_kernel<<<1024, 256>>>(attn_out_w, bv, attn_out_b, bc);
    // 9: G5 with fused qs-mix -> hqs
    gemm_fp16<2><<<dim3(8, 64), 512, GEMM_SMEM>>>(hp1, hphW2, ph_b2, hqs, 1024, 2048,
                                                  amp, rot4, rz3);
    // 10: out = qs @ Wc^T + bc (fp32 out)
    gemm_fp16<0><<<dim3(8, 64), 512, GEMM_SMEM>>>(hqs, hwc, bc, (float*)d_out, 1024, 1024,
                                                  nullptr, nullptr, nullptr);
}

// round 13
// speedup vs baseline: 1.0189x; 1.0189x over previous
#include <cuda_runtime.h>
#include <cuda_fp16.h>
#include <cstdint>
#include <math.h>

// Shapes: B=16384, Q=1024, F=2, D=5
#define NB 16384

// ---------------- scratch (device globals; no allocs allowed) ----------------
__device__ __align__(16) __half g_ha1[(size_t)NB * 4096];  // gelu(LN(...)) fp16
__device__ __align__(16) __half g_h2 [(size_t)NB * 2048];  // G2 out (pre-LN) fp16
__device__ __align__(16) __half g_ha2[(size_t)NB * 2048];  // tanh(LN(h2)) fp16
__device__ __align__(16) __half g_hp1[(size_t)NB * 2048];  // silu(LN(...)) fp16
__device__ __align__(16) __half g_amp[(size_t)NB * 1024];  // amp fp16
__device__ __align__(16) __half g_hqs[(size_t)NB * 1024];  // qs fp16
__device__ __align__(16) __half g_hw [13631488];           // half weights: W2|W3|phW2|Wo
__device__ __align__(16) __half g_hwt[1048576];            // Wv^T fp16
__device__ __align__(16) __half g_hwc[1048576];            // Wc = Wo @ Wv fp16
__device__ __align__(16) float  g_bc [1024];               // bc = Wo@bv + bo
__device__ __align__(16) float4 g_rot4[1024];              // (rf0, rp0, rf1, rp1) per col
__device__ __align__(16) float  g_rz3[1024];               // tanh(rp2)/3 per col
__device__ __align__(16) float  g_stats[18];               // 9 LN moments x 2 nets

// ---------------- helpers ----------------
__device__ __forceinline__ uint32_t smem_u32(const void* p) {
    uint32_t a;
    asm("{ .reg .u64 t; cvta.to.shared.u64 t, %1; cvt.u32.u64 %0, t; }" : "=r"(a) : "l"(p));
    return a;
}
__device__ __forceinline__ void cpa16(uint32_t saddr, const void* g) {
    asm volatile("cp.async.cg.shared.global [%0], [%1], 16;\n" :: "r"(saddr), "l"(g));
}
__device__ __forceinline__ void ldsm4(uint32_t* r, uint32_t addr) {
    asm volatile("ldmatrix.sync.aligned.m8n8.x4.shared.b16 {%0,%1,%2,%3}, [%4];"
                 : "=r"(r[0]), "=r"(r[1]), "=r"(r[2]), "=r"(r[3]) : "r"(addr));
}
__device__ __forceinline__ void mma16(float* c, const uint32_t* a, const uint32_t* b) {
    asm volatile(
        "mma.sync.aligned.m16n8k16.row.col.f32.f16.f16.f32 "
        "{%0,%1,%2,%3}, {%4,%5,%6,%7}, {%8,%9}, {%0,%1,%2,%3};\n"
        : "+f"(c[0]), "+f"(c[1]), "+f"(c[2]), "+f"(c[3])
        : "r"(a[0]), "r"(a[1]), "r"(a[2]), "r"(a[3]), "r"(b[0]), "r"(b[1]));
}
__device__ __forceinline__ float tanhfast(float x) {
    float r;
    asm("tanh.approx.f32 %0, %1;" : "=f"(r) : "f"(x));
    return r;
}
// A&S 7.1.26 erf approximation, |err| <= 1.5e-7
__device__ __forceinline__ float erf_fast(float x) {
    const float ax = fabsf(x);
    const float t = __frcp_rn(fmaf(0.3275911f, ax, 1.0f));
    float p = fmaf(1.061405429f, t, -1.453152027f);
    p = fmaf(p, t, 1.421413741f);
    p = fmaf(p, t, -0.284496736f);
    p = fmaf(p, t, 0.254829592f);
    p *= t;
    const float y = 1.0f - p * __expf(-ax * ax);
    return copysignf(y, x);
}

// ---------------- GEMM: C(M,N) = epi(A(M,K) @ W(N,K)^T + bias) ----------------
// fp16 in, fp32 accum, mma.sync m16n8k16. CTA 256x128, k-chunk 64 halves
// (128B row + 16B pad = 144B, conflict-free). 512 thr = 16 warps (8m x 2n),
// warp 32x64. 4-stage cp.async pipeline, prefetch distance 3, early issue.
// EPI: 0 = +bias -> float C; 1 = +bias -> half C;
//      2 = +bias, tanh -> qs-mix (rot4/rz3 tables) -> half C; 3 = no bias -> half C
#define ROWB 144
#define STGB (384 * ROWB)       // A 256 rows + B 128 rows = 55296 B / stage
#define NSTG 4
#define GEMM_SMEM (NSTG * STGB) // 221184

template<int EPI>
__global__ void __launch_bounds__(512, 1)
gemm_fp16(const __half* __restrict__ A, const __half* __restrict__ W,
          const float* __restrict__ bias, void* __restrict__ Cv, int N, int K,
          const __half* __restrict__ amp, const float4* __restrict__ rot4,
          const float* __restrict__ rz3) {
    extern __shared__ __align__(128) char smem[];
    const uint32_t sb = smem_u32(smem);
    const int tid = threadIdx.x, lane = tid & 31, warp = tid >> 5;
    const int wm = warp >> 1, wn = warp & 1;
    const int g = lane >> 2, tg = lane & 3;
    const int m0 = blockIdx.y * 256, n0 = blockIdx.x * 128;

    // ldmatrix per-lane byte offsets within a stage (add ks*32 at use)
    uint32_t aoff[2], boff[4];
    {
        const int arow = lane & 15, aseg = lane >> 4;
        #pragma unroll
        for (int mi = 0; mi < 2; mi++)
            aoff[mi] = (uint32_t)((wm * 32 + mi * 16 + arow) * ROWB + aseg * 16);
        const int nrow = ((lane >> 4) << 3) + (lane & 7);
        const int bseg = (lane >> 3) & 1;
        #pragma unroll
        for (int p = 0; p < 4; p++)
            boff[p] = (uint32_t)(256 * ROWB + (wn * 64 + p * 16 + nrow) * ROWB + bseg * 16);
    }

    float acc[2][8][4];
    #pragma unroll
    for (int i = 0; i < 2; i++)
        #pragma unroll
        for (int j = 0; j < 8; j++)
            #pragma unroll
            for (int k = 0; k < 4; k++) acc[i][j][k] = 0.0f;

    const int nt = K >> 6;   // k-chunks of 64 halves

    auto load_stage = [&](int t) {
        const uint32_t dst = sb + (uint32_t)(t & (NSTG - 1)) * STGB;
        // 384 rows x 8 chunks of 16B = 3072 chunks, 6 per thread
        #pragma unroll
        for (int i = 0; i < 6; i++) {
            const int cid = i * 512 + tid;
            const int r = cid >> 3, c = cid & 7;
            const __half* src = (r < 256)
                ? (A + (size_t)(m0 + r) * K + t * 64 + c * 8)
                : (W + (size_t)(n0 + r - 256) * K + t * 64 + c * 8);
            cpa16(dst + (uint32_t)(r * ROWB + c * 16), src);
        }
    };

    #pragma unroll
    for (int i = 0; i < 3; i++) {
        if (i < nt) load_stage(i);
        asm volatile("cp.async.commit_group;\n" ::: "memory");
    }

    for (int t = 0; t < nt; t++) {
        asm volatile("cp.async.wait_group 2;\n" ::: "memory");
        __syncthreads();
        // early issue of the next prefetch (stage (t+3)&3 was consumed at t-1)
        if (t + 3 < nt) load_stage(t + 3);
        asm volatile("cp.async.commit_group;\n" ::: "memory");
        const uint32_t stg = sb + (uint32_t)(t & (NSTG - 1)) * STGB;
        #pragma unroll
        for (int ks = 0; ks < 4; ks++) {   // 4 x k16 per chunk
            uint32_t af[2][4], bf[4][4];
            #pragma unroll
            for (int mi = 0; mi < 2; mi++) ldsm4(af[mi], stg + aoff[mi] + ks * 32);
            #pragma unroll
            for (int p = 0; p < 4; p++) ldsm4(bf[p], stg + boff[p] + ks * 32);
            #pragma unroll
            for (int mi = 0; mi < 2; mi++)
                #pragma unroll
                for (int ni = 0; ni < 8; ni++)
                    mma16(acc[mi][ni], af[mi], &bf[ni >> 1][(ni & 1) * 2]);
        }
    }

    // -------- epilogue --------
    #pragma unroll
    for (int mi = 0; mi < 2; mi++) {
        #pragma unroll
        for (int half_ = 0; half_ < 2; half_++) {
            const int row = m0 + wm * 32 + mi * 16 + g + half_ * 8;
            #pragma unroll
            for (int ni = 0; ni < 8; ni++) {
                const int col = n0 + wn * 64 + ni * 8 + tg * 2;
                float v0 = acc[mi][ni][half_ * 2 + 0];
                float v1 = acc[mi][ni][half_ * 2 + 1];
                if (EPI != 3) { v0 += bias[col]; v1 += bias[col + 1]; }
                if (EPI == 0) {
                    float* C = (float*)Cv;
                    *(float2*)&C[(size_t)row * N + col] = make_float2(v0, v1);
                } else if (EPI == 2) {
                    #pragma unroll
                    for (int e = 0; e < 2; e++) {
                        float& v = e ? v1 : v0;
                        const int cc = col + e;
                        const float4 rr = rot4[cc];
                        const float phase = tanhfast(v);
                        const float a = __half2float(amp[(size_t)row * 1024 + cc]);
                        const float rx = __sinf(fmaf(a, rr.x, rr.y));
                        const float ry = __cosf(fmaf(phase, rr.z, rr.w));
                        v = fmaf(rx + ry, (1.0f / 3.0f), rz3[cc]);
                    }
                    __half* C = (__half*)Cv;
                    *(__half2*)&C[(size_t)row * N + col] = __floats2half2_rn(v0, v1);
                } else {
                    __half* C = (__half*)Cv;
                    *(__half2*)&C[(size_t)row * N + col] = __floats2half2_rn(v0, v1);
                }
            }
        }
    }
}

// ---------------- block reduce helper (256-thread blocks) ----------------
__device__ __forceinline__ void blk_reduce2(float& s, float& ss) {
    __shared__ float sh[16];
    #pragma unroll
    for (int o = 16; o; o >>= 1) {
        s  += __shfl_xor_sync(0xFFFFFFFFu, s, o);
        ss += __shfl_xor_sync(0xFFFFFFFFu, ss, o);
    }
    int w = threadIdx.x >> 5, l = threadIdx.x & 31;
    if (l == 0) { sh[w] = s; sh[w + 8] = ss; }
    __syncthreads();
    if (threadIdx.x < 32) {
        float a = (l < 8) ? sh[l] : 0.0f;
        float b = (l < 8) ? sh[l + 8] : 0.0f;
        #pragma unroll
        for (int o = 4; o; o >>= 1) {
            a += __shfl_xor_sync(0xFFFFFFFFu, a, o);
            b += __shfl_xor_sync(0xFFFFFFFFu, b, o);
        }
        if (l == 0) { sh[0] = a; sh[1] = b; }
    }
    __syncthreads();
    s = sh[0]; ss = sh[1];
}

// ------------- rank-2 input layer, closed-form LN stats -------------
// ACT: 0 = gelu(fast erf), 1 = silu (fast exp).
template<int ACT, int NCOLS>
__global__ __launch_bounds__(256)
void rank2_ln_act(const float* __restrict__ x, const float* __restrict__ W,
                  const float* __restrict__ b, const float* __restrict__ gam,
                  const float* __restrict__ bet, const float* __restrict__ st,
                  __half* __restrict__ out) {
    const int row = blockIdx.x;
    const float x0 = x[row * 2], x1 = x[row * 2 + 1];
    const float mean = fmaf(x0, st[0], fmaf(x1, st[1], st[2]));
    const float var  = fmaf(x0 * x0, st[3], fmaf(x1 * x1, st[4], st[5]))
                     + 2.0f * fmaf(x0 * x1, st[6], fmaf(x0, st[7], x1 * st[8]));
    const float rstd = rsqrtf(var + 1e-5f);
    constexpr int PER2 = NCOLS / 512;
    #pragma unroll
    for (int i = 0; i < PER2; i++) {
        const int j = i * 256 + threadIdx.x;          // pair index
        const float4 w = *(const float4*)&W[4 * j];   // cols 2j, 2j+1
        const float2 bb = *(const float2*)&b[2 * j];
        const float2 gg = *(const float2*)&gam[2 * j];
        const float2 be = *(const float2*)&bet[2 * j];
        const float y0 = fmaf(x0, w.x, fmaf(x1, w.y, bb.x));
        const float y1 = fmaf(x0, w.z, fmaf(x1, w.w, bb.y));
        float r[2];
        #pragma unroll
        for (int e = 0; e < 2; e++) {
            const float v = ((e ? y1 : y0) - mean) * rstd * (e ? gg.y : gg.x)
                          + (e ? be.y : be.x);
            if (ACT == 0) r[e] = 0.5f * v * (1.0f + erf_fast(v * 0.70710678118654752f));
            else          r[e] = v * __fdividef(1.0f, 1.0f + __expf(-v));
        }
        *(__half2*)&out[(size_t)row * NCOLS + 2 * j] = __floats2half2_rn(r[0], r[1]);
    }
}

// ------------- LN + tanh (rows of 2048): fp16 in, fp16 out -------------
__global__ __launch_bounds__(256)
void ln_tanh2048(const __half* __restrict__ d, const float* __restrict__ gam,
                 const float* __restrict__ bet, __half* __restrict__ out) {
    const int row = blockIdx.x;
    float y[8];
    float s = 0.0f, ss = 0.0f;
    #pragma unroll
    for (int i = 0; i < 4; i++) {
        const int j = i * 256 + threadIdx.x;          // pair index
        const float2 v = __half22float2(*(const __half2*)&d[(size_t)row * 2048 + 2 * j]);
        y[2*i] = v.x; y[2*i+1] = v.y;
        s += v.x + v.y; ss += v.x * v.x + v.y * v.y;
    }
    blk_reduce2(s, ss);
    const float mean = s * (1.0f / 2048.0f);
    const float var  = ss * (1.0f / 2048.0f) - mean * mean;
    const float rstd = rsqrtf(var + 1e-5f);
    #pragma unroll
    for (int i = 0; i < 4; i++) {
        const int j = i * 256 + threadIdx.x;
        const float2 gg = *(const float2*)&gam[2 * j];
        const float2 be = *(const float2*)&bet[2 * j];
        const float r0 = tanhfast((y[2*i]   - mean) * rstd * gg.x + be.x);
        const float r1 = tanhfast((y[2*i+1] - mean) * rstd * gg.y + be.y);
        *(__half2*)&out[(size_t)row * 2048 + 2 * j] = __floats2half2_rn(r0, r1);
    }
}

// ------------- merged prep: weight fp16 copies + Wv transpose + rot tables + LN stats ----
__global__ __launch_bounds__(256)
void prep_weights(const float* __restrict__ W2, const float* __restrict__ W3,
                  const float* __restrict__ phW2, const float* __restrict__ Wo,
                  const float* __restrict__ Wv,
                  const float* __restrict__ aW1, const float* __restrict__ ab1,
                  const float* __restrict__ pW1, const float* __restrict__ pb1,
                  const float* __restrict__ rf, const float* __restrict__ rp,
                  __half* __restrict__ hw, __half* __restrict__ hwt,
                  float4* __restrict__ rot4, float* __restrict__ rz3,
                  float* __restrict__ stats) {
    const int bid = blockIdx.x;
    if (bid < 13312) {
        const float4* src; __half2* dst; int off;
        if (bid < 8192)       { src = (const float4*)W2;   dst = (__half2*)(hw);            off = bid; }
        else if (bid < 10240) { src = (const float4*)W3;   dst = (__half2*)(hw + 8388608);  off = bid - 8192; }
        else if (bid < 12288) { src = (const float4*)phW2; dst = (__half2*)(hw + 10485760); off = bid - 10240; }
        else                  { src = (const float4*)Wo;   dst = (__half2*)(hw + 12582912); off = bid - 12288; }
        const int i = off * 256 + threadIdx.x;
        float4 v = src[i];
        dst[2*i]   = __floats2half2_rn(v.x, v.y);
        dst[2*i+1] = __floats2half2_rn(v.z, v.w);
    } else if (bid < 14336) {
        __shared__ float t[32][33];
        const int tb = bid - 13312;
        const int bx = (tb & 31) * 32, by = (tb >> 5) * 32;
        const int tx = threadIdx.x & 31, ty = threadIdx.x >> 5;  // 32 x 8
        #pragma unroll
        for (int i = 0; i < 32; i += 8)
            t[ty + i][tx] = Wv[(size_t)(by + ty + i) * 1024 + bx + tx];
        __syncthreads();
        #pragma unroll
        for (int i = 0; i < 32; i += 8)
            hwt[(size_t)(bx + ty + i) * 1024 + by + tx] = __float2half_rn(t[tx][ty + i]);
    } else if (bid < 14338) {
        // LN weight moments in fp64
        const int net = bid - 14336;
        const float* W = net ? pW1 : aW1;
        const float* b = net ? pb1 : ab1;
        const int N = net ? 2048 : 4096;
        double a[9] = {0,0,0,0,0,0,0,0,0};
        for (int j = threadIdx.x; j < N; j += 256) {
            const double w0 = W[2*j], w1 = W[2*j+1], bb = b[j];
            a[0] += w0;    a[1] += w1;    a[2] += bb;
            a[3] += w0*w0; a[4] += w1*w1; a[5] += bb*bb;
            a[6] += w0*w1; a[7] += w0*bb; a[8] += w1*bb;
        }
        __shared__ double sh[8][9];
        const int lane = threadIdx.x & 31, w = threadIdx.x >> 5;
        #pragma unroll
        for (int k = 0; k < 9; k++)
            #pragma unroll
            for (int o = 16; o; o >>= 1)
                a[k] += __shfl_down_sync(0xFFFFFFFFu, a[k], o);
        if (lane == 0)
            #pragma unroll
            for (int k = 0; k < 9; k++) sh[w][k] = a[k];
        __syncthreads();
        if (threadIdx.x == 0) {
            double S[9];
            #pragma unroll
            for (int k = 0; k < 9; k++) {
                S[k] = 0.0;
                for (int ww = 0; ww < 8; ww++) S[k] += sh[ww][k];
            }
            const double inv = 1.0 / N;
            const double m0 = S[0]*inv, m1 = S[1]*inv, mb = S[2]*inv;
            float* st = stats + 9 * net;
            st[0] = (float)m0; st[1] = (float)m1; st[2] = (float)mb;
            st[3] = (float)(S[3]*inv - m0*m0);
            st[4] = (float)(S[4]*inv - m1*m1);
            st[5] = (float)(S[5]*inv - mb*mb);
            st[6] = (float)(S[6]*inv - m0*m1);
            st[7] = (float)(S[7]*inv - m0*mb);
            st[8] = (float)(S[8]*inv - m1*mb);
        }
    } else {
        // rot tables (d = 4 slice)
        for (int j = threadIdx.x; j < 1024; j += 256) {
            const int base = (4 * 1024 + j) * 3;
            rot4[j] = make_float4(rf[base], rp[base], rf[base + 1], rp[base + 1]);
            rz3[j]  = tanhf(rp[base + 2]) * (1.0f / 3.0f);
        }
    }
}

// ------------- bc = Wo @ bv + bo (fp32) -------------
__global__ __launch_bounds__(256)
void bc_kernel(const float* __restrict__ Wo, const float* __restrict__ bv,
               const float* __restrict__ bo, float* __restrict__ bc) {
    const int row = blockIdx.x;
    float s = 0.0f, ss = 0.0f;
    for (int k = threadIdx.x; k < 1024; k += 256)
        s += Wo[(size_t)row * 1024 + k] * bv[k];
    blk_reduce2(s, ss);
    if (threadIdx.x == 0) bc[row] = s + bo[row];
}

// ---------------- launch ----------------
extern "C" void kernel_launch(void* const* d_in, const int* in_sizes, int n_in,
                              void* d_out, int out_size) {
    const float* x        = (const float*)d_in[0];
    const float* amp_W1   = (const float*)d_in[1];
    const float* amp_b1   = (const float*)d_in[2];
    const float* amp_g1   = (const float*)d_in[3];
    const float* amp_be1  = (const float*)d_in[4];
    const float* amp_W2   = (const float*)d_in[5];
    const float* amp_b2   = (const float*)d_in[6];
    const float* amp_g2   = (const float*)d_in[7];
    const float* amp_be2  = (const float*)d_in[8];
    const float* amp_W3   = (const float*)d_in[9];
    const float* amp_b3   = (const float*)d_in[10];
    const float* ph_W1    = (const float*)d_in[11];
    const float* ph_b1    = (const float*)d_in[12];
    const float* ph_g1    = (const float*)d_in[13];
    const float* ph_be1   = (const float*)d_in[14];
    const float* ph_W2    = (const float*)d_in[15];
    const float* ph_b2    = (const float*)d_in[16];
    const float* rot_freq = (const float*)d_in[17];
    const float* rot_phase= (const float*)d_in[18];
    const float* attn_in_w= (const float*)d_in[19];
    const float* attn_in_b= (const float*)d_in[20];
    const float* attn_out_w=(const float*)d_in[21];
    const float* attn_out_b=(const float*)d_in[22];

    float *bc, *rz3, *stats;
    float4* rot4;
    __half *ha1, *h2, *ha2, *hp1, *amp, *hqs, *hw, *hwt, *hwc;
    cudaGetSymbolAddress((void**)&ha1, g_ha1);
    cudaGetSymbolAddress((void**)&h2,  g_h2);
    cudaGetSymbolAddress((void**)&ha2, g_ha2);
    cudaGetSymbolAddress((void**)&hp1, g_hp1);
    cudaGetSymbolAddress((void**)&amp, g_amp);
    cudaGetSymbolAddress((void**)&hqs, g_hqs);
    cudaGetSymbolAddress((void**)&hw,  g_hw);
    cudaGetSymbolAddress((void**)&hwt, g_hwt);
    cudaGetSymbolAddress((void**)&hwc, g_hwc);
    cudaGetSymbolAddress((void**)&bc,  g_bc);
    cudaGetSymbolAddress((void**)&rot4, g_rot4);
    cudaGetSymbolAddress((void**)&rz3, g_rz3);
    cudaGetSymbolAddress((void**)&stats, g_stats);

    __half* hW2   = hw;
    __half* hW3   = hw + 8388608;
    __half* hphW2 = hw + 10485760;
    __half* hWo   = hw + 12582912;
    const float* Wv = attn_in_w + (size_t)2048 * 1024;
    const float* bv = attn_in_b + 2048;

    cudaFuncSetAttribute(gemm_fp16<0>, cudaFuncAttributeMaxDynamicSharedMemorySize, GEMM_SMEM);
    cudaFuncSetAttribute(gemm_fp16<1>, cudaFuncAttributeMaxDynamicSharedMemorySize, GEMM_SMEM);
    cudaFuncSetAttribute(gemm_fp16<2>, cudaFuncAttributeMaxDynamicSharedMemorySize, GEMM_SMEM);
    cudaFuncSetAttribute(gemm_fp16<3>, cudaFuncAttributeMaxDynamicSharedMemorySize, GEMM_SMEM);

    // 1: merged prep (weights, transpose, rot tables, LN stats)
    prep_weights<<<14339, 256>>>(amp_W2, amp_W3, ph_W2, attn_out_w, Wv,
                                 amp_W1, amp_b1, ph_W1, ph_b1, rot_freq, rot_phase,
                                 hw, hwt, rot4, rz3, stats);
    // 2: Wc = Wo @ Wv (A=hWo, W=hWv^T), half out
    gemm_fp16<3><<<dim3(8, 4), 512, GEMM_SMEM>>>(hWo, hwt, nullptr, hwc, 1024, 1024,
                                                 nullptr, nullptr, nullptr);
    // 3: amp input layer (closed-form LN, fast erf)
    rank2_ln_act<0, 4096><<<NB, 256>>>(x, amp_W1, amp_b1, amp_g1, amp_be1, stats, ha1);
    // 4: G2 (big GEMM -> ncu captured slot)
    gemm_fp16<1><<<dim3(16, 64), 512, GEMM_SMEM>>>(ha1, hW2, amp_b2, h2, 2048, 4096,
                                                   nullptr, nullptr, nullptr);
    // 5: phase input layer
    rank2_ln_act<1, 2048><<<NB, 256>>>(x, ph_W1, ph_b1, ph_g1, ph_be1, stats + 9, hp1);
    // 6: LN + tanh
    ln_tanh2048<<<NB, 256>>>(h2, amp_g2, amp_be2, ha2);
    // 7: G3 -> amp (fp16)
    gemm_fp16<1><<<dim3(8, 64), 512, GEMM_SMEM>>>(ha2, hW3, amp_b3, amp, 1024, 2048,
                                                  nullptr, nullptr, nullptr);
    // 8: bc = Wo@bv + bo
    bc_kernel<<<1024, 256>>>(attn_out_w, bv, attn_out_b, bc);
    // 9: G5 with fused qs-mix -> hqs
    gemm_fp16<2><<<dim3(8, 64), 512, GEMM_SMEM>>>(hp1, hphW2, ph_b2, hqs, 1024, 2048,
                                                  amp, rot4, rz3);
    // 10: out = qs @ Wc^T + bc (fp32 out)
    gemm_fp16<0><<<dim3(8, 64), 512, GEMM_SMEM>>>(hqs, hwc, bc, (float*)d_out, 1024, 1024,
                                                  nullptr, nullptr, nullptr);
}

// round 14
// speedup vs baseline: 1.1567x; 1.1352x over previous
#include <cuda_runtime.h>
#include <cuda_fp16.h>
#include <cstdint>
#include <math.h>

// Shapes: B=16384, Q=1024, F=2, D=5
#define NB 16384

// ---------------- scratch (device globals; no allocs allowed) ----------------
__device__ __align__(16) __half g_ha1[(size_t)NB * 4096];  // gelu(LN(...)) fp16
__device__ __align__(16) __half g_h2 [(size_t)NB * 2048];  // G2 out (pre-LN) fp16
__device__ __align__(16) __half g_ha2[(size_t)NB * 2048];  // tanh(LN(h2)) fp16
__device__ __align__(16) __half g_hp1[(size_t)NB * 2048];  // silu(LN(...)) fp16
__device__ __align__(16) __half g_amp[(size_t)NB * 1024];  // amp fp16
__device__ __align__(16) __half g_hqs[(size_t)NB * 1024];  // qs fp16
__device__ __align__(16) __half g_hw [13631488];           // half weights: W2|W3|phW2|Wo
__device__ __align__(16) __half g_hwt[1048576];            // Wv^T fp16
__device__ __align__(16) __half g_hwc[1048576];            // Wc = Wo @ Wv fp16
__device__ __align__(16) float  g_bc [1024];               // bc = Wo@bv + bo
__device__ __align__(16) float4 g_rot4[1024];              // (rf0, rp0, rf1, rp1) per col
__device__ __align__(16) float  g_rz3[1024];               // tanh(rp2)/3 per col
__device__ __align__(16) float  g_stats[18];               // 9 LN moments x 2 nets

// ---------------- helpers ----------------
__device__ __forceinline__ uint32_t smem_u32(const void* p) {
    uint32_t a;
    asm("{ .reg .u64 t; cvta.to.shared.u64 t, %1; cvt.u32.u64 %0, t; }" : "=r"(a) : "l"(p));
    return a;
}
__device__ __forceinline__ void cpa16(uint32_t saddr, const void* g) {
    asm volatile("cp.async.cg.shared.global [%0], [%1], 16;\n" :: "r"(saddr), "l"(g));
}
__device__ __forceinline__ void ldsm4(uint32_t* r, uint32_t addr) {
    asm volatile("ldmatrix.sync.aligned.m8n8.x4.shared.b16 {%0,%1,%2,%3}, [%4];"
                 : "=r"(r[0]), "=r"(r[1]), "=r"(r[2]), "=r"(r[3]) : "r"(addr));
}
__device__ __forceinline__ void mma16(float* c, const uint32_t* a, const uint32_t* b) {
    asm volatile(
        "mma.sync.aligned.m16n8k16.row.col.f32.f16.f16.f32 "
        "{%0,%1,%2,%3}, {%4,%5,%6,%7}, {%8,%9}, {%0,%1,%2,%3};\n"
        : "+f"(c[0]), "+f"(c[1]), "+f"(c[2]), "+f"(c[3])
        : "r"(a[0]), "r"(a[1]), "r"(a[2]), "r"(a[3]), "r"(b[0]), "r"(b[1]));
}
__device__ __forceinline__ float tanhfast(float x) {
    float r;
    asm("tanh.approx.f32 %0, %1;" : "=f"(r) : "f"(x));
    return r;
}
// A&S 7.1.26 erf approximation, |err| <= 1.5e-7
__device__ __forceinline__ float erf_fast(float x) {
    const float ax = fabsf(x);
    const float t = __frcp_rn(fmaf(0.3275911f, ax, 1.0f));
    float p = fmaf(1.061405429f, t, -1.453152027f);
    p = fmaf(p, t, 1.421413741f);
    p = fmaf(p, t, -0.284496736f);
    p = fmaf(p, t, 0.254829592f);
    p *= t;
    const float y = 1.0f - p * __expf(-ax * ax);
    return copysignf(y, x);
}

// ---------------- GEMM: C(M,N) = epi(A(M,K) @ W(N,K)^T + bias) ----------------
// fp16 in, fp32 accum, mma.sync m16n8k16. CTA tile 128x128, k-chunk 64 halves
// (128B row + 16B pad = 144B, conflict-free). 256 thr = 8 warps (4m x 2n),
// warp 32x64. 3-stage cp.async ring, 2 CTAs/SM for cross-CTA latency hiding.
// EPI: 0 = +bias -> float C; 1 = +bias -> half C;
//      2 = +bias, tanh -> qs-mix (rot4/rz3 tables) -> half C; 3 = no bias -> half C
#define ROWB 144
#define STGB (256 * ROWB)       // A 128 rows + B 128 rows = 36864 B / stage
#define NSTG 3
#define GEMM_SMEM (NSTG * STGB) // 110592 per CTA (x2 CTAs = 221184 per SM)

template<int EPI>
__global__ void __launch_bounds__(256, 2)
gemm_fp16(const __half* __restrict__ A, const __half* __restrict__ W,
          const float* __restrict__ bias, void* __restrict__ Cv, int N, int K,
          const __half* __restrict__ amp, const float4* __restrict__ rot4,
          const float* __restrict__ rz3) {
    extern __shared__ __align__(128) char smem[];
    const uint32_t sb = smem_u32(smem);
    const int tid = threadIdx.x, lane = tid & 31, warp = tid >> 5;
    const int wm = warp >> 1, wn = warp & 1;
    const int g = lane >> 2, tg = lane & 3;
    const int m0 = blockIdx.y * 128, n0 = blockIdx.x * 128;

    // ldmatrix per-lane byte offsets within a stage (add ks*32 at use)
    uint32_t aoff[2], boff[4];
    {
        const int arow = lane & 15, aseg = lane >> 4;
        #pragma unroll
        for (int mi = 0; mi < 2; mi++)
            aoff[mi] = (uint32_t)((wm * 32 + mi * 16 + arow) * ROWB + aseg * 16);
        const int nrow = ((lane >> 4) << 3) + (lane & 7);
        const int bseg = (lane >> 3) & 1;
        #pragma unroll
        for (int p = 0; p < 4; p++)
            boff[p] = (uint32_t)(128 * ROWB + (wn * 64 + p * 16 + nrow) * ROWB + bseg * 16);
    }

    float acc[2][8][4];
    #pragma unroll
    for (int i = 0; i < 2; i++)
        #pragma unroll
        for (int j = 0; j < 8; j++)
            #pragma unroll
            for (int k = 0; k < 4; k++) acc[i][j][k] = 0.0f;

    const int nt = K >> 6;   // k-chunks of 64 halves

    auto load_stage = [&](int t) {
        const uint32_t dst = sb + (uint32_t)(t % NSTG) * STGB;
        // 256 rows x 8 chunks of 16B = 2048 chunks, 8 per thread
        #pragma unroll
        for (int i = 0; i < 8; i++) {
            const int cid = i * 256 + tid;
            const int r = cid >> 3, c = cid & 7;
            const __half* src = (r < 128)
                ? (A + (size_t)(m0 + r) * K + t * 64 + c * 8)
                : (W + (size_t)(n0 + r - 128) * K + t * 64 + c * 8);
            cpa16(dst + (uint32_t)(r * ROWB + c * 16), src);
        }
        asm volatile("cp.async.commit_group;\n" ::: "memory");
    };

    load_stage(0);
    load_stage(1);

    for (int t = 0; t < nt; t++) {
        asm volatile("cp.async.wait_group 1;\n" ::: "memory");
        __syncthreads();
        const uint32_t stg = sb + (uint32_t)(t % NSTG) * STGB;
        #pragma unroll
        for (int ks = 0; ks < 4; ks++) {   // 4 x k16 per chunk
            uint32_t af[2][4], bf[4][4];
            #pragma unroll
            for (int mi = 0; mi < 2; mi++) ldsm4(af[mi], stg + aoff[mi] + ks * 32);
            #pragma unroll
            for (int p = 0; p < 4; p++) ldsm4(bf[p], stg + boff[p] + ks * 32);
            #pragma unroll
            for (int mi = 0; mi < 2; mi++)
                #pragma unroll
                for (int ni = 0; ni < 8; ni++)
                    mma16(acc[mi][ni], af[mi], &bf[ni >> 1][(ni & 1) * 2]);
        }
        if (t + 2 < nt) load_stage(t + 2);
        else asm volatile("cp.async.commit_group;\n" ::: "memory");
    }

    // -------- epilogue --------
    #pragma unroll
    for (int mi = 0; mi < 2; mi++) {
        #pragma unroll
        for (int half_ = 0; half_ < 2; half_++) {
            const int row = m0 + wm * 32 + mi * 16 + g + half_ * 8;
            #pragma unroll
            for (int ni = 0; ni < 8; ni++) {
                const int col = n0 + wn * 64 + ni * 8 + tg * 2;
                float v0 = acc[mi][ni][half_ * 2 + 0];
                float v1 = acc[mi][ni][half_ * 2 + 1];
                if (EPI != 3) { v0 += bias[col]; v1 += bias[col + 1]; }
                if (EPI == 0) {
                    float* C = (float*)Cv;
                    *(float2*)&C[(size_t)row * N + col] = make_float2(v0, v1);
                } else if (EPI == 2) {
                    #pragma unroll
                    for (int e = 0; e < 2; e++) {
                        float& v = e ? v1 : v0;
                        const int cc = col + e;
                        const float4 rr = rot4[cc];
                        const float phase = tanhfast(v);
                        const float a = __half2float(amp[(size_t)row * 1024 + cc]);
                        const float rx = __sinf(fmaf(a, rr.x, rr.y));
                        const float ry = __cosf(fmaf(phase, rr.z, rr.w));
                        v = fmaf(rx + ry, (1.0f / 3.0f), rz3[cc]);
                    }
                    __half* C = (__half*)Cv;
                    *(__half2*)&C[(size_t)row * N + col] = __floats2half2_rn(v0, v1);
                } else {
                    __half* C = (__half*)Cv;
                    *(__half2*)&C[(size_t)row * N + col] = __floats2half2_rn(v0, v1);
                }
            }
        }
    }
}

// ---------------- block reduce helper (256-thread blocks) ----------------
__device__ __forceinline__ void blk_reduce2(float& s, float& ss) {
    __shared__ float sh[16];
    #pragma unroll
    for (int o = 16; o; o >>= 1) {
        s  += __shfl_xor_sync(0xFFFFFFFFu, s, o);
        ss += __shfl_xor_sync(0xFFFFFFFFu, ss, o);
    }
    int w = threadIdx.x >> 5, l = threadIdx.x & 31;
    if (l == 0) { sh[w] = s; sh[w + 8] = ss; }
    __syncthreads();
    if (threadIdx.x < 32) {
        float a = (l < 8) ? sh[l] : 0.0f;
        float b = (l < 8) ? sh[l + 8] : 0.0f;
        #pragma unroll
        for (int o = 4; o; o >>= 1) {
            a += __shfl_xor_sync(0xFFFFFFFFu, a, o);
            b += __shfl_xor_sync(0xFFFFFFFFu, b, o);
        }
        if (l == 0) { sh[0] = a; sh[1] = b; }
    }
    __syncthreads();
    s = sh[0]; ss = sh[1];
}

// ------------- rank-2 input layer, closed-form LN stats -------------
// ACT: 0 = gelu(fast erf), 1 = silu (fast exp).
template<int ACT, int NCOLS>
__global__ __launch_bounds__(256)
void rank2_ln_act(const float* __restrict__ x, const float* __restrict__ W,
                  const float* __restrict__ b, const float* __restrict__ gam,
                  const float* __restrict__ bet, const float* __restrict__ st,
                  __half* __restrict__ out) {
    const int row = blockIdx.x;
    const float x0 = x[row * 2], x1 = x[row * 2 + 1];
    const float mean = fmaf(x0, st[0], fmaf(x1, st[1], st[2]));
    const float var  = fmaf(x0 * x0, st[3], fmaf(x1 * x1, st[4], st[5]))
                     + 2.0f * fmaf(x0 * x1, st[6], fmaf(x0, st[7], x1 * st[8]));
    const float rstd = rsqrtf(var + 1e-5f);
    constexpr int PER2 = NCOLS / 512;
    #pragma unroll
    for (int i = 0; i < PER2; i++) {
        const int j = i * 256 + threadIdx.x;          // pair index
        const float4 w = *(const float4*)&W[4 * j];   // cols 2j, 2j+1
        const float2 bb = *(const float2*)&b[2 * j];
        const float2 gg = *(const float2*)&gam[2 * j];
        const float2 be = *(const float2*)&bet[2 * j];
        const float y0 = fmaf(x0, w.x, fmaf(x1, w.y, bb.x));
        const float y1 = fmaf(x0, w.z, fmaf(x1, w.w, bb.y));
        float r[2];
        #pragma unroll
        for (int e = 0; e < 2; e++) {
            const float v = ((e ? y1 : y0) - mean) * rstd * (e ? gg.y : gg.x)
                          + (e ? be.y : be.x);
            if (ACT == 0) r[e] = 0.5f * v * (1.0f + erf_fast(v * 0.70710678118654752f));
            else          r[e] = v * __fdividef(1.0f, 1.0f + __expf(-v));
        }
        *(__half2*)&out[(size_t)row * NCOLS + 2 * j] = __floats2half2_rn(r[0], r[1]);
    }
}

// ------------- LN + tanh (rows of 2048): fp16 in, fp16 out -------------
__global__ __launch_bounds__(256)
void ln_tanh2048(const __half* __restrict__ d, const float* __restrict__ gam,
                 const float* __restrict__ bet, __half* __restrict__ out) {
    const int row = blockIdx.x;
    float y[8];
    float s = 0.0f, ss = 0.0f;
    #pragma unroll
    for (int i = 0; i < 4; i++) {
        const int j = i * 256 + threadIdx.x;          // pair index
        const float2 v = __half22float2(*(const __half2*)&d[(size_t)row * 2048 + 2 * j]);
        y[2*i] = v.x; y[2*i+1] = v.y;
        s += v.x + v.y; ss += v.x * v.x + v.y * v.y;
    }
    blk_reduce2(s, ss);
    const float mean = s * (1.0f / 2048.0f);
    const float var  = ss * (1.0f / 2048.0f) - mean * mean;
    const float rstd = rsqrtf(var + 1e-5f);
    #pragma unroll
    for (int i = 0; i < 4; i++) {
        const int j = i * 256 + threadIdx.x;
        const float2 gg = *(const float2*)&gam[2 * j];
        const float2 be = *(const float2*)&bet[2 * j];
        const float r0 = tanhfast((y[2*i]   - mean) * rstd * gg.x + be.x);
        const float r1 = tanhfast((y[2*i+1] - mean) * rstd * gg.y + be.y);
        *(__half2*)&out[(size_t)row * 2048 + 2 * j] = __floats2half2_rn(r0, r1);
    }
}

// ------------- merged prep: weight fp16 copies + Wv transpose + rot tables + LN stats ----
__global__ __launch_bounds__(256)
void prep_weights(const float* __restrict__ W2, const float* __restrict__ W3,
                  const float* __restrict__ phW2, const float* __restrict__ Wo,
                  const float* __restrict__ Wv,
                  const float* __restrict__ aW1, const float* __restrict__ ab1,
                  const float* __restrict__ pW1, const float* __restrict__ pb1,
                  const float* __restrict__ rf, const float* __restrict__ rp,
                  __half* __restrict__ hw, __half* __restrict__ hwt,
                  float4* __restrict__ rot4, float* __restrict__ rz3,
                  float* __restrict__ stats) {
    const int bid = blockIdx.x;
    if (bid < 13312) {
        const float4* src; __half2* dst; int off;
        if (bid < 8192)       { src = (const float4*)W2;   dst = (__half2*)(hw);            off = bid; }
        else if (bid < 10240) { src = (const float4*)W3;   dst = (__half2*)(hw + 8388608);  off = bid - 8192; }
        else if (bid < 12288) { src = (const float4*)phW2; dst = (__half2*)(hw + 10485760); off = bid - 10240; }
        else                  { src = (const float4*)Wo;   dst = (__half2*)(hw + 12582912); off = bid - 12288; }
        const int i = off * 256 + threadIdx.x;
        float4 v = src[i];
        dst[2*i]   = __floats2half2_rn(v.x, v.y);
        dst[2*i+1] = __floats2half2_rn(v.z, v.w);
    } else if (bid < 14336) {
        __shared__ float t[32][33];
        const int tb = bid - 13312;
        const int bx = (tb & 31) * 32, by = (tb >> 5) * 32;
        const int tx = threadIdx.x & 31, ty = threadIdx.x >> 5;  // 32 x 8
        #pragma unroll
        for (int i = 0; i < 32; i += 8)
            t[ty + i][tx] = Wv[(size_t)(by + ty + i) * 1024 + bx + tx];
        __syncthreads();
        #pragma unroll
        for (int i = 0; i < 32; i += 8)
            hwt[(size_t)(bx + ty + i) * 1024 + by + tx] = __float2half_rn(t[tx][ty + i]);
    } else if (bid < 14338) {
        // LN weight moments in fp64
        const int net = bid - 14336;
        const float* W = net ? pW1 : aW1;
        const float* b = net ? pb1 : ab1;
        const int N = net ? 2048 : 4096;
        double a[9] = {0,0,0,0,0,0,0,0,0};
        for (int j = threadIdx.x; j < N; j += 256) {
            const double w0 = W[2*j], w1 = W[2*j+1], bb = b[j];
            a[0] += w0;    a[1] += w1;    a[2] += bb;
            a[3] += w0*w0; a[4] += w1*w1; a[5] += bb*bb;
            a[6] += w0*w1; a[7] += w0*bb; a[8] += w1*bb;
        }
        __shared__ double sh[8][9];
        const int lane = threadIdx.x & 31, w = threadIdx.x >> 5;
        #pragma unroll
        for (int k = 0; k < 9; k++)
            #pragma unroll
            for (int o = 16; o; o >>= 1)
                a[k] += __shfl_down_sync(0xFFFFFFFFu, a[k], o);
        if (lane == 0)
            #pragma unroll
            for (int k = 0; k < 9; k++) sh[w][k] = a[k];
        __syncthreads();
        if (threadIdx.x == 0) {
            double S[9];
            #pragma unroll
            for (int k = 0; k < 9; k++) {
                S[k] = 0.0;
                for (int ww = 0; ww < 8; ww++) S[k] += sh[ww][k];
            }
            const double inv = 1.0 / N;
            const double m0 = S[0]*inv, m1 = S[1]*inv, mb = S[2]*inv;
            float* st = stats + 9 * net;
            st[0] = (float)m0; st[1] = (float)m1; st[2] = (float)mb;
            st[3] = (float)(S[3]*inv - m0*m0);
            st[4] = (float)(S[4]*inv - m1*m1);
            st[5] = (float)(S[5]*inv - mb*mb);
            st[6] = (float)(S[6]*inv - m0*m1);
            st[7] = (float)(S[7]*inv - m0*mb);
            st[8] = (float)(S[8]*inv - m1*mb);
        }
    } else {
        // rot tables (d = 4 slice)
        for (int j = threadIdx.x; j < 1024; j += 256) {
            const int base = (4 * 1024 + j) * 3;
            rot4[j] = make_float4(rf[base], rp[base], rf[base + 1], rp[base + 1]);
            rz3[j]  = tanhf(rp[base + 2]) * (1.0f / 3.0f);
        }
    }
}

// ------------- bc = Wo @ bv + bo (fp32) -------------
__global__ __launch_bounds__(256)
void bc_kernel(const float* __restrict__ Wo, const float* __restrict__ bv,
               const float* __restrict__ bo, float* __restrict__ bc) {
    const int row = blockIdx.x;
    float s = 0.0f, ss = 0.0f;
    for (int k = threadIdx.x; k < 1024; k += 256)
        s += Wo[(size_t)row * 1024 + k] * bv[k];
    blk_reduce2(s, ss);
    if (threadIdx.x == 0) bc[row] = s + bo[row];
}

// ---------------- launch ----------------
extern "C" void kernel_launch(void* const* d_in, const int* in_sizes, int n_in,
                              void* d_out, int out_size) {
    const float* x        = (const float*)d_in[0];
    const float* amp_W1   = (const float*)d_in[1];
    const float* amp_b1   = (const float*)d_in[2];
    const float* amp_g1   = (const float*)d_in[3];
    const float* amp_be1  = (const float*)d_in[4];
    const float* amp_W2   = (const float*)d_in[5];
    const float* amp_b2   = (const float*)d_in[6];
    const float* amp_g2   = (const float*)d_in[7];
    const float* amp_be2  = (const float*)d_in[8];
    const float* amp_W3   = (const float*)d_in[9];
    const float* amp_b3   = (const float*)d_in[10];
    const float* ph_W1    = (const float*)d_in[11];
    const float* ph_b1    = (const float*)d_in[12];
    const float* ph_g1    = (const float*)d_in[13];
    const float* ph_be1   = (const float*)d_in[14];
    const float* ph_W2    = (const float*)d_in[15];
    const float* ph_b2    = (const float*)d_in[16];
    const float* rot_freq = (const float*)d_in[17];
    const float* rot_phase= (const float*)d_in[18];
    const float* attn_in_w= (const float*)d_in[19];
    const float* attn_in_b= (const float*)d_in[20];
    const float* attn_out_w=(const float*)d_in[21];
    const float* attn_out_b=(const float*)d_in[22];

    float *bc, *rz3, *stats;
    float4* rot4;
    __half *ha1, *h2, *ha2, *hp1, *amp, *hqs, *hw, *hwt, *hwc;
    cudaGetSymbolAddress((void**)&ha1, g_ha1);
    cudaGetSymbolAddress((void**)&h2,  g_h2);
    cudaGetSymbolAddress((void**)&ha2, g_ha2);
    cudaGetSymbolAddress((void**)&hp1, g_hp1);
    cudaGetSymbolAddress((void**)&amp, g_amp);
    cudaGetSymbolAddress((void**)&hqs, g_hqs);
    cudaGetSymbolAddress((void**)&hw,  g_hw);
    cudaGetSymbolAddress((void**)&hwt, g_hwt);
    cudaGetSymbolAddress((void**)&hwc, g_hwc);
    cudaGetSymbolAddress((void**)&bc,  g_bc);
    cudaGetSymbolAddress((void**)&rot4, g_rot4);
    cudaGetSymbolAddress((void**)&rz3, g_rz3);
    cudaGetSymbolAddress((void**)&stats, g_stats);

    __half* hW2   = hw;
    __half* hW3   = hw + 8388608;
    __half* hphW2 = hw + 10485760;
    __half* hWo   = hw + 12582912;
    const float* Wv = attn_in_w + (size_t)2048 * 1024;
    const float* bv = attn_in_b + 2048;

    cudaFuncSetAttribute(gemm_fp16<0>, cudaFuncAttributeMaxDynamicSharedMemorySize, GEMM_SMEM);
    cudaFuncSetAttribute(gemm_fp16<1>, cudaFuncAttributeMaxDynamicSharedMemorySize, GEMM_SMEM);
    cudaFuncSetAttribute(gemm_fp16<2>, cudaFuncAttributeMaxDynamicSharedMemorySize, GEMM_SMEM);
    cudaFuncSetAttribute(gemm_fp16<3>, cudaFuncAttributeMaxDynamicSharedMemorySize, GEMM_SMEM);

    // 1: merged prep (weights, transpose, rot tables, LN stats)
    prep_weights<<<14339, 256>>>(amp_W2, amp_W3, ph_W2, attn_out_w, Wv,
                                 amp_W1, amp_b1, ph_W1, ph_b1, rot_freq, rot_phase,
                                 hw, hwt, rot4, rz3, stats);
    // 2: Wc = Wo @ Wv (A=hWo, W=hWv^T), half out
    gemm_fp16<3><<<dim3(8, 8), 256, GEMM_SMEM>>>(hWo, hwt, nullptr, hwc, 1024, 1024,
                                                 nullptr, nullptr, nullptr);
    // 3: amp input layer (closed-form LN, fast erf)
    rank2_ln_act<0, 4096><<<NB, 256>>>(x, amp_W1, amp_b1, amp_g1, amp_be1, stats, ha1);
    // 4: G2 (big GEMM -> ncu captured slot)
    gemm_fp16<1><<<dim3(16, 128), 256, GEMM_SMEM>>>(ha1, hW2, amp_b2, h2, 2048, 4096,
                                                    nullptr, nullptr, nullptr);
    // 5: phase input layer
    rank2_ln_act<1, 2048><<<NB, 256>>>(x, ph_W1, ph_b1, ph_g1, ph_be1, stats + 9, hp1);
    // 6: LN + tanh
    ln_tanh2048<<<NB, 256>>>(h2, amp_g2, amp_be2, ha2);
    // 7: G3 -> amp (fp16)
    gemm_fp16<1><<<dim3(8, 128), 256, GEMM_SMEM>>>(ha2, hW3, amp_b3, amp, 1024, 2048,
                                                   nullptr, nullptr, nullptr);
    // 8: bc = Wo@bv + bo
    bc_kernel<<<1024, 256>>>(attn_out_w, bv, attn_out_b, bc);
    // 9: G5 with fused qs-mix -> hqs
    gemm_fp16<2><<<dim3(8, 128), 256, GEMM_SMEM>>>(hp1, hphW2, ph_b2, hqs, 1024, 2048,
                                                   amp, rot4, rz3);
    // 10: out = qs @ Wc^T + bc (fp32 out)
    gemm_fp16<0><<<dim3(8, 128), 256, GEMM_SMEM>>>(hqs, hwc, bc, (float*)d_out, 1024, 1024,
                                                   nullptr, nullptr, nullptr);
}